// round 16
// baseline (speedup 1.0000x reference)
#include <cuda_runtime.h>
#include <cstdint>

// ---------------------------------------------------------------------------
// Seq2seq BiLSTM (encoder 336 + autoregressive decoder 24), persistent kernel.
//
// Grid = 128 CTAs = 2 dirs x 4 batch-tiles(32) x 16 j-tiles(16), 512 thr/CTA.
// 4-WAY SPLIT-K: group hg = tid>>7 handles x-k [16hg,16hg+16) before the flag
// wait and h-k [64+64hg,128+64hg) after. Thread: 4 batch rows x 4 gates of one
// hidden unit (f32x2 gate pairs) over its K quarter; finalizes row bi==hg
// after a symmetric 4-way partial exchange through padded smem.
// QUADS: warps {q, q+4, q+8, q+12} share batch rows 8q..8q+8; staging and the
// exchange sync with named barrier (q+1, 128). Flag wait is warp-local.
// One __syncthreads per round (flag release). W fetched as one LDS.128
// (gates i,f|g,o). AS=332 keeps A LDS.128 conflict-free.
// g_h double-buffered by parity; release/acquire flags, 16-CTA groups.
// ---------------------------------------------------------------------------

#define NBLK 128
#define NTHR 512

namespace {
constexpr int BATCH = 128;
constexpr int SEQLEN = 336;
constexpr int PRED = 24;
constexpr int IN = 64;
constexpr int HID = 256;
constexpr int KTOT = IN + HID;          // 320
constexpr int WS = 68;                  // W smem row stride (floats)
constexpr int AS = 332;                 // A row stride (conflict-free pairs)
constexpr int RED_U64 = 128 * 25;       // 12 slots*2 u64 + pad, per tid7
constexpr int SMEM_FLOATS = KTOT * WS + 32 * AS + 64 + RED_U64 * 2;
constexpr int SMEM_BYTES = SMEM_FLOATS * 4;   // 155392 B
}

__device__ float g_h[2][2 * BATCH * HID];       // [parity][dir*BATCH+b][HID]
__device__ float g_y[PRED * BATCH * IN];
__device__ int   g_flags[NBLK];

using u64 = unsigned long long;

__device__ __forceinline__ int ld_acq(const int* p) {
    int v;
    asm volatile("ld.global.acquire.gpu.b32 %0, [%1];" : "=r"(v) : "l"(p) : "memory");
    return v;
}
__device__ __forceinline__ void st_rel(int* p, int v) {
    asm volatile("st.global.release.gpu.b32 [%0], %1;" :: "l"(p), "r"(v) : "memory");
}
__device__ __forceinline__ u64 ffma2(u64 a, u64 b, u64 c) {
    u64 d;
    asm("fma.rn.f32x2 %0, %1, %2, %3;" : "=l"(d) : "l"(a), "l"(b), "l"(c));
    return d;
}
__device__ __forceinline__ u64 fadd2(u64 a, u64 b) {
    u64 d;
    asm("add.rn.f32x2 %0, %1, %2;" : "=l"(d) : "l"(a), "l"(b));
    return d;
}
__device__ __forceinline__ u64 pack2(float lo, float hi) {
    u64 d;
    asm("mov.b64 %0, {%1, %2};" : "=l"(d) : "f"(lo), "f"(hi));
    return d;
}
__device__ __forceinline__ void unpack2(float& lo, float& hi, u64 v) {
    asm("mov.b64 {%0, %1}, %2;" : "=f"(lo), "=f"(hi) : "l"(v));
}
__device__ __forceinline__ float fsig(float x) {
    return __fdividef(1.0f, 1.0f + __expf(-x));
}
__device__ __forceinline__ float ftanh(float x) {
    float ax = fabsf(x);
    float t = __expf(-2.0f * ax);
    float r = __fdividef(1.0f - t, 1.0f + t);
    return copysignf(r, x);
}

__device__ __forceinline__ void quadbar(int q) {
    asm volatile("bar.sync %0, 128;" :: "r"(q + 1) : "memory");
}
__device__ __forceinline__ void release(int v) {
    __syncthreads();
    if (threadIdx.x == 0) st_rel(&g_flags[blockIdx.x], v);
}
__device__ __forceinline__ void waitf(int base, int cnt, int v) {
    if (threadIdx.x < cnt) {
        const int* p = &g_flags[base + threadIdx.x];
        while (ld_acq(p) < v) { }
    }
    __syncthreads();
}
__device__ __forceinline__ void pollflag(int idx, int v) {
    const int* p = &g_flags[idx];
    while (ld_acq(p) < v) { }
}

// W slice -> SMEM: Wsm[k*WS + jj*4 + g], source row = g*256 + j0 + jj.
__device__ void load_phase_weights(float* Wsm, float* bsum,
                                   const float* __restrict__ Wih,
                                   const float* __restrict__ Whh,
                                   const float* __restrict__ bih,
                                   const float* __restrict__ bhh,
                                   int d, int j0) {
    for (int idx = threadIdx.x; idx < 64 * KTOT; idx += NTHR) {
        int c = idx / KTOT;
        int k = idx - c * KTOT;
        int jj = c >> 2, g = c & 3;
        int row = g * 256 + j0 + jj;
        float v = (k < IN) ? Wih[(d * 1024 + row) * IN + k]
                           : Whh[(d * 1024 + row) * HID + (k - IN)];
        Wsm[k * WS + c] = v;
    }
    for (int c = threadIdx.x; c < 64; c += NTHR) {
        int jj = c >> 2, g = c & 3;
        int row = g * 256 + j0 + jj;
        bsum[c] = bih[d * 1024 + row] + bhh[d * 1024 + row];
    }
}

// Packed f32x2 GEMM over k range [k0,k1); 4 rows x (i,f),(g,o) pairs.
__device__ __forceinline__ void gemm_span(const float* Asm, const float* Wsm,
                                          int tj, int tb, int k0, int k1,
                                          u64 acc[4][2]) {
    const float* A0 = Asm + (tb * 4) * AS;
#pragma unroll 4
    for (int k = k0; k < k1; k += 4) {
        float4 a0 = *(const float4*)(A0 + k);
        float4 a1 = *(const float4*)(A0 + AS + k);
        float4 a2 = *(const float4*)(A0 + 2 * AS + k);
        float4 a3 = *(const float4*)(A0 + 3 * AS + k);
        float av[4][4] = {{a0.x, a0.y, a0.z, a0.w},
                          {a1.x, a1.y, a1.z, a1.w},
                          {a2.x, a2.y, a2.z, a2.w},
                          {a3.x, a3.y, a3.z, a3.w}};
#pragma unroll
        for (int kk = 0; kk < 4; kk++) {
            ulonglong2 w = *(const ulonglong2*)(Wsm + (k + kk) * WS + tj * 4);
#pragma unroll
            for (int bi = 0; bi < 4; bi++) {
                u64 ad = pack2(av[bi][kk], av[bi][kk]);
                acc[bi][0] = ffma2(ad, w.x, acc[bi][0]);
                acc[bi][1] = ffma2(ad, w.y, acc[bi][1]);
            }
        }
    }
}

// One LSTM step; quad-local staging + 4-way split-K + quartered pointwise.
__device__ __forceinline__ void cell_step(const float* __restrict__ src,
                                          int rowStride, int d, int b0, int j0,
                                          const float* __restrict__ hsrc,
                                          float* __restrict__ hdst,
                                          const float* Wsm, float* Asm,
                                          u64* redsm, const float* bsum,
                                          float& c_reg, int round, int gbase,
                                          int hg, int quad, int qtid, int lane,
                                          int tid7, int tj, int tb) {
    // ---- 1. stage x rows [8q, 8q+8), 16 f4/row; 1 f4 per thread
    {
        int row = quad * 8 + (qtid >> 4);
        int f4 = qtid & 15;
        float4 v = __ldcg((const float4*)(src + (size_t)(b0 + row) * rowStride) + f4);
        *(float4*)(Asm + row * AS + f4 * 4) = v;
    }
    quadbar(quad);

    // ---- 2. acc init + pre-wait x-GEMM (group hg: k 16hg..16hg+16)
    u64 acc[4][2];
    if (hg == 0) {
        float4 bv = *(const float4*)(bsum + tj * 4);
        u64 b01 = pack2(bv.x, bv.y);
        u64 b23 = pack2(bv.z, bv.w);
#pragma unroll
        for (int bi = 0; bi < 4; bi++) { acc[bi][0] = b01; acc[bi][1] = b23; }
    } else {
#pragma unroll
        for (int bi = 0; bi < 4; bi++) { acc[bi][0] = 0ull; acc[bi][1] = 0ull; }
    }
    gemm_span(Asm, Wsm, tj, tb, hg * 16, hg * 16 + 16, acc);

    // ---- 3. warp-local wait on the 16 group flags
    if (lane < 16) pollflag(gbase + lane, round);
    __syncwarp();

    // ---- 4. stage h rows [8q, 8q+8), 64 f4/row; 4 f4 per thread
    float4 v[4];
#pragma unroll
    for (int u = 0; u < 4; u++) {
        int idx = qtid + u * 128;                 // 0..511
        int row8 = idx >> 6;
        int slot = idx & 63;
        v[u] = __ldcg((const float4*)(hsrc +
                (size_t)((d << 7) + b0 + quad * 8 + row8) * HID) + slot);
    }
#pragma unroll
    for (int u = 0; u < 4; u++) {
        int idx = qtid + u * 128;
        int row8 = idx >> 6;
        int slot = idx & 63;
        *(float4*)(Asm + (quad * 8 + row8) * AS + IN + slot * 4) = v[u];
    }
    quadbar(quad);

    // ---- 5. h-GEMM (group hg: k 64+64hg .. 128+64hg)
    gemm_span(Asm, Wsm, tj, tb, IN + hg * 64, IN + hg * 64 + 64, acc);

    // ---- 6. 4-way partial exchange: store rows bi != hg
    {
        u64* r = redsm + (size_t)tid7 * 25;
#pragma unroll
        for (int bi = 0; bi < 4; bi++) {
            if (bi != hg) {
                int si = hg * 3 + (bi > hg ? bi - 1 : bi);
                r[si * 2 + 0] = acc[bi][0];
                r[si * 2 + 1] = acc[bi][1];
            }
        }
    }
    quadbar(quad);

    // ---- 7. finalize own row (bi == hg): sum 4 partials, pointwise, store h
    {
        const u64* r = redsm + (size_t)tid7 * 25;
        u64 s01 = acc[hg][0];
        u64 s23 = acc[hg][1];
#pragma unroll
        for (int g = 0; g < 4; g++) {
            if (g != hg) {
                int si = g * 3 + (hg > g ? hg - 1 : hg);
                s01 = fadd2(s01, r[si * 2 + 0]);
                s23 = fadd2(s23, r[si * 2 + 1]);
            }
        }
        float gi, gf, gg, go;
        unpack2(gi, gf, s01);
        unpack2(gg, go, s23);
        float cn = fsig(gf) * c_reg + fsig(gi) * ftanh(gg);
        float hn = fsig(go) * ftanh(cn);
        c_reg = cn;
        int row = tb * 4 + hg;
        hdst[(size_t)((d << 7) + b0 + row) * HID + j0 + tj] = hn;
    }
}

__global__ void __launch_bounds__(NTHR, 1)
lstm_s2s_kernel(const float* __restrict__ x,
                const float* __restrict__ eWih, const float* __restrict__ eWhh,
                const float* __restrict__ ebih, const float* __restrict__ ebhh,
                const float* __restrict__ dWih, const float* __restrict__ dWhh,
                const float* __restrict__ dbih, const float* __restrict__ dbhh,
                const float* __restrict__ linW, const float* __restrict__ linb,
                float* __restrict__ out) {
    extern __shared__ float smem[];
    float* Wsm  = smem;                        // [320][68]
    float* Asm  = Wsm + KTOT * WS;             // [32][332]
    float* bsum = Asm + 32 * AS;               // [64]
    u64*   redsm = (u64*)(bsum + 64);          // [128][25] u64
    float* redf = (float*)redsm;               // projection scratch [512]

    const int ct = blockIdx.x;
    const int d = ct >> 6;
    const int rem = ct & 63;
    const int b0 = (rem >> 4) * 32;
    const int j0 = (rem & 15) * 16;
    const int gbase = ct & ~15;                // 16 CTAs sharing (dir, b-tile)
    const int tid = threadIdx.x;
    const int hg = tid >> 7;                   // K quarter (0..3)
    const int tid7 = tid & 127;
    const int lane = tid & 31;
    const int quad = (tid >> 5) & 3;           // row-quad id
    const int qtid = hg * 32 + lane;           // 0..127 within quad
    const int tj = tid7 & 15;
    const int tb = tid7 >> 4;                  // 0..7

    float c_reg = 0.f;
    int hr = 0;

    // fresh state every replay: zero own h slice in buffer 0 (1 elt/thread)
    {
        int bb = tid >> 4;                     // tid < 512 = 32*16
        int jj = tid & 15;
        g_h[0][(size_t)((d << 7) + b0 + bb) * HID + j0 + jj] = 0.f;
    }
    release(1);
    int round = 1;

    load_phase_weights(Wsm, bsum, eWih, eWhh, ebih, ebhh, d, j0);
    __syncthreads();

    // ===== encoder =====
    for (int r = 0; r < SEQLEN; r++) {
        int t = (d == 0) ? r : (SEQLEN - 1 - r);
        cell_step(x + t * IN, SEQLEN * IN, d, b0, j0,
                  g_h[hr & 1], g_h[(hr + 1) & 1],
                  Wsm, Asm, redsm, bsum, c_reg, round, gbase,
                  hg, quad, qtid, lane, tid7, tj, tb);
        hr++;
        release(round + 1); round++;
    }

    // ===== switch to decoder weights =====
    load_phase_weights(Wsm, bsum, dWih, dWhh, dbih, dbhh, d, j0);
    __syncthreads();

    // ===== decoder: 24 autoregressive iterations =====
    for (int t = 0; t < PRED; t++) {
        int L = (t == 0) ? 1 : t;
        for (int s = 0; s < L; s++) {
            const float* src;
            int stride;
            if (t == 0) {
                src = x + (SEQLEN - 1) * IN;       // x[:, -1, :]
                stride = SEQLEN * IN;
            } else {
                int yi = (d == 0) ? s : (L - 1 - s);
                src = g_y + (size_t)yi * BATCH * IN;
                stride = IN;
            }
            cell_step(src, stride, d, b0, j0,
                      g_h[hr & 1], g_h[(hr + 1) & 1],
                      Wsm, Asm, redsm, bsum, c_reg, round, gbase,
                      hg, quad, qtid, lane, tid7, tj, tb);
            hr++;
            release(round + 1); round++;
        }

        // ---- projection (CTAs 0..63): y = concat(hF,hB) @ linW^T + linb
        if (ct < 64) {
            if (tid < 32) {                        // producers of this b-tile
                int base = (ct >> 4) * 16;
                pollflag(base + (tid & 15) + ((tid & 16) ? 64 : 0), round);
            }
            __syncthreads();
            const float* hb = g_h[hr & 1];
            int bsel = tid >> 8;                   // 0..1
            int q4 = (tid >> 6) & 3;               // quarter of the 512-dot
            int col = tid & 63;
            int b = (ct << 1) + bsel;
            const float4* w4 = (const float4*)(linW + col * (2 * HID)) + q4 * 32;
            const float4* hv = (q4 < 2)
                ? (const float4*)(hb + (size_t)b * HID) + q4 * 32
                : (const float4*)(hb + (size_t)(BATCH + b) * HID) + (q4 - 2) * 32;
            float s = 0.f;
#pragma unroll 8
            for (int q = 0; q < 32; q++) {
                float4 f = __ldcg(hv + q);
                float4 w = __ldg(w4 + q);
                s += f.x * w.x + f.y * w.y + f.z * w.z + f.w * w.w;
            }
            redf[tid] = s;
            __syncthreads();
            if (q4 == 0) {
                float rv = redf[tid] + redf[tid + 64] + redf[tid + 128]
                         + redf[tid + 192] + linb[col];
                g_y[((size_t)t * BATCH + b) * IN + col] = rv;
                out[((size_t)b * PRED + t) * IN + col] = rv;
            }
        }
        release(round + 1); round++;
        // g_y rows for this b-tile come from projection CTAs [b0/2, b0/2+16)
        waitf(b0 >> 1, 16, round);
    }
}

extern "C" void kernel_launch(void* const* d_in, const int* in_sizes, int n_in,
                              void* d_out, int out_size) {
    const float* x    = (const float*)d_in[0];
    const float* eWih = (const float*)d_in[1];
    const float* eWhh = (const float*)d_in[2];
    const float* ebih = (const float*)d_in[3];
    const float* ebhh = (const float*)d_in[4];
    const float* dWih = (const float*)d_in[5];
    const float* dWhh = (const float*)d_in[6];
    const float* dbih = (const float*)d_in[7];
    const float* dbhh = (const float*)d_in[8];
    const float* linW = (const float*)d_in[9];
    const float* linb = (const float*)d_in[10];
    float* out = (float*)d_out;

    void* flagsPtr = nullptr;
    cudaGetSymbolAddress(&flagsPtr, g_flags);
    cudaMemsetAsync(flagsPtr, 0, sizeof(int) * NBLK, 0);

    cudaFuncSetAttribute(lstm_s2s_kernel,
                         cudaFuncAttributeMaxDynamicSharedMemorySize, SMEM_BYTES);

    lstm_s2s_kernel<<<NBLK, NTHR, SMEM_BYTES>>>(
        x, eWih, eWhh, ebih, ebhh, dWih, dWhh, dbih, dbhh, linW, linb, out);
}